// round 14
// baseline (speedup 1.0000x reference)
#include <cuda_runtime.h>
#include <cuda_bf16.h>
#include <cuda_fp16.h>
#include <math.h>

#define BB 2
#define SS 2048
#define HH 16
#define DKx 1024
#define DVx 1024
#define BSx (BB*SS)
#define EC (0.125f*1.4426950408889634f)

__device__ __nv_bfloat16 g_xb [BSx*DKx];
__device__ __nv_bfloat16 g_Wqb[DKx*DKx];
__device__ __nv_bfloat16 g_Wkb[DKx*DKx];
__device__ __nv_bfloat16 g_Wvb[DKx*DKx];
__device__ __nv_bfloat16 g_Wdb[DKx*DKx];
__device__ __nv_bfloat16 g_mixb[HH*DKx];
__device__ __nv_bfloat16 g_q  [BSx*DKx];
__device__ __nv_bfloat16 g_k  [BSx*DKx];
__device__ __nv_bfloat16 g_v  [BSx*DVx];   // fp16 bits
__device__ unsigned char g_q8 [(size_t)HH*BSx*DKx];
__device__ unsigned char g_k8 [(size_t)BSx*DKx];
__device__ float         g_cb [BSx*HH];
__device__ __nv_bfloat16 g_ctx[BSx*DVx];
__device__ float         g_res[BSx*DVx];

static __device__ __forceinline__ unsigned sptr(const void* p){
    return (unsigned)__cvta_generic_to_shared(p);
}
static __device__ __forceinline__ void ldm4(unsigned&r0,unsigned&r1,unsigned&r2,unsigned&r3,unsigned a){
    asm volatile("ldmatrix.sync.aligned.m8n8.x4.shared.b16 {%0,%1,%2,%3},[%4];\n"
        :"=r"(r0),"=r"(r1),"=r"(r2),"=r"(r3):"r"(a));
}
static __device__ __forceinline__ void ldm4t(unsigned&r0,unsigned&r1,unsigned&r2,unsigned&r3,unsigned a){
    asm volatile("ldmatrix.sync.aligned.m8n8.x4.trans.shared.b16 {%0,%1,%2,%3},[%4];\n"
        :"=r"(r0),"=r"(r1),"=r"(r2),"=r"(r3):"r"(a));
}
static __device__ __forceinline__ void mma16816(float* c,unsigned a0,unsigned a1,unsigned a2,unsigned a3,
                                                unsigned b0,unsigned b1){
    asm volatile("mma.sync.aligned.m16n8k16.row.col.f32.bf16.bf16.f32 "
        "{%0,%1,%2,%3},{%4,%5,%6,%7},{%8,%9},{%0,%1,%2,%3};\n"
        :"+f"(c[0]),"+f"(c[1]),"+f"(c[2]),"+f"(c[3])
        :"r"(a0),"r"(a1),"r"(a2),"r"(a3),"r"(b0),"r"(b1));
}
static __device__ __forceinline__ void mma16816h(float* c,unsigned a0,unsigned a1,unsigned a2,unsigned a3,
                                                 unsigned b0,unsigned b1){
    asm volatile("mma.sync.aligned.m16n8k16.row.col.f32.f16.f16.f32 "
        "{%0,%1,%2,%3},{%4,%5,%6,%7},{%8,%9},{%0,%1,%2,%3};\n"
        :"+f"(c[0]),"+f"(c[1]),"+f"(c[2]),"+f"(c[3])
        :"r"(a0),"r"(a1),"r"(a2),"r"(a3),"r"(b0),"r"(b1));
}
static __device__ __forceinline__ void mma16832(float* c,unsigned a0,unsigned a1,unsigned a2,unsigned a3,
                                                unsigned b0,unsigned b1){
    asm volatile("mma.sync.aligned.m16n8k32.row.col.f32.e4m3.e4m3.f32 "
        "{%0,%1,%2,%3},{%4,%5,%6,%7},{%8,%9},{%0,%1,%2,%3};\n"
        :"+f"(c[0]),"+f"(c[1]),"+f"(c[2]),"+f"(c[3])
        :"r"(a0),"r"(a1),"r"(a2),"r"(a3),"r"(b0),"r"(b1));
}
static __device__ __forceinline__ unsigned pk8(float f0,float f1,float f2,float f3){
    unsigned r;
    asm("{\n\t.reg .b16 lo,hi;\n\t"
        "cvt.rn.satfinite.e4m3x2.f32 lo, %2, %1;\n\t"
        "cvt.rn.satfinite.e4m3x2.f32 hi, %4, %3;\n\t"
        "mov.b32 %0,{lo,hi};\n\t}"
        :"=r"(r):"f"(f0),"f"(f1),"f"(f2),"f"(f3));
    return r;
}
static __device__ __forceinline__ void cpa16(unsigned d,const void* s){
    asm volatile("cp.async.cg.shared.global [%0],[%1],16;"::"r"(d),"l"(s):"memory");
}
#define CPCOMMIT() asm volatile("cp.async.commit_group;":::"memory")
#define CPWAIT(n)  asm volatile("cp.async.wait_group %0;"::"n"(n):"memory")

__global__ void __launch_bounds__(256) cvt_all(const float* __restrict__ x,const float* __restrict__ wq,
        const float* __restrict__ wk,const float* __restrict__ wv,const float* __restrict__ wd,
        const float* __restrict__ mx){
    int bx=blockIdx.x; const float* s; __nv_bfloat16* d; long base;
    if(bx<4096){s=x;d=g_xb;base=bx;}
    else if(bx<5120){s=wq;d=g_Wqb;base=bx-4096;}
    else if(bx<6144){s=wk;d=g_Wkb;base=bx-5120;}
    else if(bx<7168){s=wv;d=g_Wvb;base=bx-6144;}
    else if(bx<8192){s=wd;d=g_Wdb;base=bx-7168;}
    else {s=mx;d=g_mixb;base=bx-8192;}
    size_t off=(size_t)base*1024 + threadIdx.x*4;
    float4 v=*(const float4*)(s+off);
    *(__nv_bfloat162*)(d+off)  =__floats2bfloat162_rn(v.x,v.y);
    *(__nv_bfloat162*)(d+off+2)=__floats2bfloat162_rn(v.z,v.w);
}

__global__ void __launch_bounds__(256) gemm_k(const __nv_bfloat16* __restrict__ A,
        const __nv_bfloat16* __restrict__ Bw,const float* __restrict__ bias,
        const float* __restrict__ resid,void* outp,int mode){
    __shared__ __align__(16) __nv_bfloat16 as_[128*72];
    __shared__ __align__(16) __nv_bfloat16 bs_[128*72];
    int f16o=0;
    if(mode==3){
        int z=blockIdx.z;
        Bw=(z==0)?g_Wqb:(z==1)?g_Wkb:g_Wvb;
        outp=(z==0)?(void*)g_q:(z==1)?(void*)g_k:(void*)g_v;
        if(z!=2) bias=nullptr; else f16o=1;
        mode=0;
    }
    const int m0=blockIdx.x*128,n0=blockIdx.y*128;
    const int tid=threadIdx.x,wr=tid>>5,ln=tid&31,g=ln>>2,tg=ln&3;
    const int mg=wr&3,nh=wr>>2;
    const unsigned asb=sptr(as_),bsb=sptr(bs_);
    float acc[64];
#pragma unroll
    for(int i=0;i<64;i++) acc[i]=0.f;
    for(int c0=0;c0<1024;c0+=64){
        __syncthreads();
#pragma unroll
        for(int t=0;t<4;t++){
            int idx=tid+t*256,row=idx>>3,cv=(idx&7)*8;
            *(uint4*)((char*)as_+(row*72+cv)*2)=*(const uint4*)(A +(size_t)(m0+row)*1024+c0+cv);
            *(uint4*)((char*)bs_+(row*72+cv)*2)=*(const uint4*)(Bw+(size_t)(n0+row)*1024+c0+cv);
        }
        __syncthreads();
#pragma unroll
        for(int kk=0;kk<4;kk++){
            unsigned a[2][4];
#pragma unroll
            for(int af=0;af<2;af++)
                ldm4(a[af][0],a[af][1],a[af][2],a[af][3],
                     asb+((mg*32+af*16+(ln&15))*72+kk*16+((ln>>4)<<3))*2);
#pragma unroll
            for(int nb=0;nb<4;nb++){
                unsigned b0,b1,b2,b3;
                int brow=nh*64+nb*16+(ln&7)+((ln&16)?8:0),bcol=kk*16+((ln&8)?8:0);
                ldm4(b0,b1,b2,b3,bsb+(brow*72+bcol)*2);
#pragma unroll
                for(int af=0;af<2;af++){
                    mma16816(acc+((af*4+nb)*2  )*4,a[af][0],a[af][1],a[af][2],a[af][3],b0,b1);
                    mma16816(acc+((af*4+nb)*2+1)*4,a[af][0],a[af][1],a[af][2],a[af][3],b2,b3);
                }
            }
        }
    }
#pragma unroll
    for(int af=0;af<2;af++){
        const int r0=m0+mg*32+af*16+g;
#pragma unroll
        for(int nb=0;nb<4;nb++)
#pragma unroll
        for(int p=0;p<2;p++){
            int col=n0+nh*64+nb*16+p*8+2*tg;
            float* ap=acc+((af*4+nb)*2+p)*4;
            if(mode==2){
                float* out=(float*)outp;
                float b0=bias[col],b1=bias[col+1];
                *(float2*)(out+(size_t)r0*1024+col)=make_float2(
                    ap[0]+b0+resid[(size_t)r0*1024+col],
                    ap[1]+b1+resid[(size_t)r0*1024+col+1]);
                *(float2*)(out+(size_t)(r0+8)*1024+col)=make_float2(
                    ap[2]+b0+resid[(size_t)(r0+8)*1024+col],
                    ap[3]+b1+resid[(size_t)(r0+8)*1024+col+1]);
            }else{
                __nv_bfloat16* out=(__nv_bfloat16*)outp;
                float b0=bias?bias[col]:0.f,b1=bias?bias[col+1]:0.f;
                if(f16o){
                    *(__half2*)(out+(size_t)r0*1024+col)    =__floats2half2_rn(ap[0]+b0,ap[1]+b1);
                    *(__half2*)(out+(size_t)(r0+8)*1024+col)=__floats2half2_rn(ap[2]+b0,ap[3]+b1);
                }else{
                    *(__nv_bfloat162*)(out+(size_t)r0*1024+col)    =__floats2bfloat162_rn(ap[0]+b0,ap[1]+b1);
                    *(__nv_bfloat162*)(out+(size_t)(r0+8)*1024+col)=__floats2bfloat162_rn(ap[2]+b0,ap[3]+b1);
                }
            }
        }
    }
}

__global__ void __launch_bounds__(256) prep8(const float* __restrict__ x,const float* __restrict__ Wcb){
    int bx=blockIdx.x,tid=threadIdx.x;
    if(bx<4096){
        __shared__ float xr[1024];
        int s=bx;
        for(int t=tid;t<1024;t+=256) xr[t]=x[(size_t)s*1024+t];
        __syncthreads();
        int w=tid>>5,ln=tid&31;
#pragma unroll
        for(int j=0;j<2;j++){
            int h=w*2+j;
            const float* wrow=Wcb+(size_t)h*1024;
            float sum=0.f;
            for(int c=ln;c<1024;c+=32) sum+=xr[c]*wrow[c];
#pragma unroll
            for(int off=16;off;off>>=1) sum+=__shfl_xor_sync(0xffffffffu,sum,off);
            if(ln==0) g_cb[(size_t)s*HH+h]=sum;
        }
    }else if(bx<8192){
        int row=bx-4096, col=tid*4;
        const __nv_bfloat162* q2=(const __nv_bfloat162*)(g_q+(size_t)row*1024+col);
        float2 q0=__bfloat1622float2(q2[0]),q1=__bfloat1622float2(q2[1]);
#pragma unroll
        for(int h=0;h<HH;h++){
            const __nv_bfloat162* m2=(const __nv_bfloat162*)(g_mixb+(size_t)h*1024+col);
            float2 m0=__bfloat1622float2(m2[0]),m1=__bfloat1622float2(m2[1]);
            unsigned p=pk8(q0.x*m0.x,q0.y*m0.y,q1.x*m1.x,q1.y*m1.y);
            *(unsigned*)(g_q8+((size_t)h*4096+row)*1024+col)=p;
        }
    }else{
        size_t off=((size_t)(bx-8192)*256+tid)*4;
        const __nv_bfloat162* k2=(const __nv_bfloat162*)(g_k+off);
        float2 k0=__bfloat1622float2(k2[0]),k1=__bfloat1622float2(k2[1]);
        *(unsigned*)(g_k8+off)=pk8(k0.x,k0.y,k1.x,k1.y);
    }
}

// ---------- FP8 flash, 4-stage ring, TWO chunks per barrier ----------
#define STG  15360u
#define OVS  61440u
#define OPS  79872u
#define OCBS 97280u
#define ORL  97792u
#define FSM  98816

__global__ void __launch_bounds__(256,2) flash_k(){
    extern __shared__ __align__(16) char sm[];
    const int b=blockIdx.z,h=blockIdx.y,i0=blockIdx.x*64;
    const int tid=threadIdx.x,wr=tid>>5,ln=tid&31,g=ln>>2,tg=ln&3;
    const int mg=wr&1,ng=wr>>1;      // score: 32 rows x 32 keys
    const int pmg=wr&3,pnh=wr>>2;    // PV: 16 rows x 32 vcols
    const unsigned sb=sptr(sm);
    float* cbs=(float*)(sm+OCBS);
    float* rlP=(float*)(sm+ORL);
    const unsigned char* q8g=g_q8+((size_t)h*4096+b*2048+i0)*1024;
    const unsigned char* k8g=g_k8+(size_t)(b*2048)*1024;
    const __nv_bfloat16* vg=g_v+(size_t)(b*SS)*DVx;

    const unsigned char* qsrc=q8g+(size_t)(tid>>2)*1024+(tid&3)*16;
    const unsigned  qdst=sb+(unsigned)((tid>>2)*80+(tid&3)*16);
    const unsigned char* ksrc=k8g+(size_t)(tid>>2)*1024+(tid&3)*16;
    const unsigned  kdst=sb+5120u+(unsigned)((tid>>2)*80+(tid&3)*16);
    const __nv_bfloat16* vsrc=vg+(size_t)(tid>>3)*1024+(size_t)h*64+(tid&7)*8;
    const unsigned  vdst=sb+OVS+(unsigned)(((tid>>3)*72+(tid&7)*8)*2);
    const unsigned qoff=(unsigned)((mg*32+(ln&15))*80+((ln>>4)<<4));
    const unsigned koff=5120u+(unsigned)((ng*32+(ln&7)+((ln&16)?8:0))*80+((ln&8)?16:0));
    const unsigned poff=sb+OPS+(unsigned)(((pmg*16+(ln&15))*136+((ln>>4)<<3))*2);
    const unsigned voff=sb+OVS+(unsigned)((((ln&7)+((ln&8)?8:0))*72+pnh*32+((ln&16)?8:0))*2);

    float sacc[32],octx[16];
    float lsA[2][2]={{0.f,0.f},{0.f,0.f}};
#pragma unroll
    for(int i=0;i<16;i++) octx[i]=0.f;

    auto issue=[&](unsigned stg,int c0,int j0){
        cpa16(qdst+stg*STG, qsrc+c0);
        cpa16(kdst+stg*STG,       ksrc+(size_t)j0*1024+c0);
        cpa16(kdst+stg*STG+5120u, ksrc+(size_t)(j0+64)*1024+c0);
    };
    auto issueV=[&](int j0){
#pragma unroll
        for(int t=0;t<4;t++)
            cpa16(vdst+(unsigned)(t*32*72*2), vsrc+(size_t)(j0+t*32)*1024);
    };
    auto score=[&](int c){   // one chunk's LDSM+MMA from stage c&3
        const unsigned base=sb+(unsigned)((c&3)*STG);
#pragma unroll
        for(int kk=0;kk<2;kk++){
            unsigned a[2][4],bq[2][4];
#pragma unroll
            for(int rf=0;rf<2;rf++)
                ldm4(a[rf][0],a[rf][1],a[rf][2],a[rf][3],base+qoff+rf*1280u+kk*32);
#pragma unroll
            for(int kf=0;kf<2;kf++)
                ldm4(bq[kf][0],bq[kf][1],bq[kf][2],bq[kf][3],base+koff+kf*1280u+kk*32);
#pragma unroll
            for(int rf=0;rf<2;rf++)
#pragma unroll
            for(int kf=0;kf<2;kf++){
                mma16832(sacc+(rf*4+kf*2  )*4,a[rf][0],a[rf][1],a[rf][2],a[rf][3],bq[kf][0],bq[kf][1]);
                mma16832(sacc+(rf*4+kf*2+1)*4,a[rf][0],a[rf][1],a[rf][2],a[rf][3],bq[kf][2],bq[kf][3]);
            }
        }
    };

    issue(0,0,0);   CPCOMMIT();
    issue(1,64,0);  CPCOMMIT();
    issue(2,128,0); CPCOMMIT();
    issue(3,192,0); CPCOMMIT();

    for(int jt=0;jt<16;jt++){
        const int j0=jt*128;
#pragma unroll
        for(int i=0;i<32;i++) sacc[i]=0.f;
#pragma unroll
        for(int cc=0;cc<8;cc++){
            if(cc==7&&jt==15){ CPWAIT(0); } else { CPWAIT(2); }
            __syncthreads();
            if(cc==0&&tid<128) cbs[tid]=g_cb[(size_t)(b*SS+j0+tid)*HH+h]*EC;
            score(2*cc); score(2*cc+1);
            if(cc<5){
                issue((2*cc)&3,(2*cc+4)*64,j0);   CPCOMMIT();
                issue((2*cc+1)&3,(2*cc+5)*64,j0); CPCOMMIT();
            }else if(cc==5){
                issue(2,896,j0); CPCOMMIT();
                issue(3,960,j0); issueV(j0); CPCOMMIT();
            }else if(jt<15){
                int nb0=(cc-6)*2;   // 0,2 -> next-jt chunks 0..3
                issue((nb0)&3,nb0*64,j0+128);     CPCOMMIT();
                issue((nb0+1)&3,(nb0+1)*64,j0+128); CPCOMMIT();
            }
        }
        // fp16 softmax epilogue
        {
#pragma unroll
            for(int rf=0;rf<2;rf++){
                int r0=mg*32+rf*16+g;
                unsigned hs0=0,hs1=0;
#pragma unroll
                for(int kf=0;kf<2;kf++)
#pragma unroll
                for(int nf=0;nf<2;nf++){
                    float* sp=sacc+(rf*4+kf*2+nf)*4;
                    int col=ng*32+kf*16+nf*8+2*tg;
                    float c0v=cbs[col],c1v=cbs[col+1];
                    float s0=fmaf(sp[0],EC,c0v),s1=fmaf(sp[1],EC,c1v);
                    float s2=fmaf(sp[2],EC,c0v),s3=fmaf(sp[3],EC,c1v);
                    unsigned u0,u1,p0,p1;
                    asm("cvt.rn.f16x2.f32 %0,%1,%2;":"=r"(u0):"f"(s1),"f"(s0));
                    asm("cvt.rn.f16x2.f32 %0,%1,%2;":"=r"(u1):"f"(s3),"f"(s2));
                    asm("ex2.approx.f16x2 %0,%1;":"=r"(p0):"r"(u0));
                    asm("ex2.approx.f16x2 %0,%1;":"=r"(p1):"r"(u1));
                    asm("add.rn.f16x2 %0,%1,%2;":"=r"(hs0):"r"(hs0),"r"(p0));
                    asm("add.rn.f16x2 %0,%1,%2;":"=r"(hs1):"r"(hs1),"r"(p1));
                    *(unsigned*)(sm+OPS+((size_t)r0*136+col)*2)    =p0;
                    *(unsigned*)(sm+OPS+((size_t)(r0+8)*136+col)*2)=p1;
                }
                float2 f0=__half22float2(*(__half2*)&hs0);
                float2 f1=__half22float2(*(__half2*)&hs1);
                lsA[rf][0]+=f0.x+f0.y; lsA[rf][1]+=f1.x+f1.y;
            }
        }
        __syncthreads();   // P complete; V arrived (waited at cc=7)
#pragma unroll
        for(int kb2=0;kb2<8;kb2++){
            unsigned p0,p1,p2,p3;
            ldm4(p0,p1,p2,p3,poff+(unsigned)(kb2*32));
#pragma unroll
            for(int vp=0;vp<2;vp++){
                unsigned b0,b1,b2,b3;
                ldm4t(b0,b1,b2,b3,voff+(unsigned)((kb2*16*72+vp*16)*2));
                mma16816h(octx+(2*vp  )*4,p0,p1,p2,p3,b0,b1);
                mma16816h(octx+(2*vp+1)*4,p0,p1,p2,p3,b2,b3);
            }
        }
    }
#pragma unroll
    for(int rf=0;rf<2;rf++)
#pragma unroll
    for(int hf=0;hf<2;hf++){
        float v=lsA[rf][hf];
        v+=__shfl_xor_sync(0xffffffffu,v,1);
        v+=__shfl_xor_sync(0xffffffffu,v,2);
        if(tg==0) rlP[ng*64+mg*32+rf*16+hf*8+g]=v;
    }
    __syncthreads();
    int rr=pmg*16+g;
    float inv0=1.f/(rlP[rr]  +rlP[64+rr]  +rlP[128+rr]  +rlP[192+rr]);
    float inv1=1.f/(rlP[rr+8]+rlP[64+rr+8]+rlP[128+rr+8]+rlP[192+rr+8]);
    int r0=i0+rr;
    __nv_bfloat16* cg=g_ctx+(size_t)(b*SS)*DVx+h*64;
#pragma unroll
    for(int i=0;i<4;i++){
        int col=pnh*32+i*8+2*tg;
        *(__nv_bfloat162*)(cg+(size_t)r0*DVx+col)=
            __floats2bfloat162_rn(octx[i*4+0]*inv0,octx[i*4+1]*inv0);
        *(__nv_bfloat162*)(cg+(size_t)(r0+8)*DVx+col)=
            __floats2bfloat162_rn(octx[i*4+2]*inv1,octx[i*4+3]*inv1);
    }
}

__global__ void __launch_bounds__(256) ln_k(const float* __restrict__ gamma,
        const float* __restrict__ beta,float* __restrict__ out){
    int s=blockIdx.x,tid=threadIdx.x;
    const float* r=g_res+(size_t)s*1024;
    float sum=0.f,sq=0.f;
#pragma unroll
    for(int i=tid;i<1024;i+=256){ float v=r[i]; sum+=v; sq+=v*v; }
#pragma unroll
    for(int off=16;off;off>>=1){
        sum+=__shfl_xor_sync(0xffffffffu,sum,off);
        sq +=__shfl_xor_sync(0xffffffffu,sq ,off);
    }
    __shared__ float ss[8],sv[8];
    if((tid&31)==0){ ss[tid>>5]=sum; sv[tid>>5]=sq; }
    __syncthreads();
    float tot=0.f,tot2=0.f;
#pragma unroll
    for(int i=0;i<8;i++){ tot+=ss[i]; tot2+=sv[i]; }
    float mu=tot*(1.f/1024.f),var=tot2*(1.f/1024.f)-mu*mu;
    float is=rsqrtf(var+1e-5f);
    for(int i=tid;i<1024;i+=256)
        out[(size_t)s*1024+i]=(r[i]-mu)*is*gamma[i]+beta[i];
}

extern "C" void kernel_launch(void* const* d_in,const int* in_sizes,int n_in,
                              void* d_out,int out_size){
    const float* x    =(const float*)d_in[0];
    const float* Wq   =(const float*)d_in[1];
    const float* Wk   =(const float*)d_in[2];
    const float* Wcb  =(const float*)d_in[3];
    const float* Wv   =(const float*)d_in[4];
    const float* bv   =(const float*)d_in[5];
    const float* mixing=(const float*)d_in[6];
    const float* Wd   =(const float*)d_in[7];
    const float* bd   =(const float*)d_in[8];
    const float* gamma=(const float*)d_in[9];
    const float* beta =(const float*)d_in[10];
    float* out=(float*)d_out;

    void *xb,*wdb,*ctxb,*resp;
    cudaGetSymbolAddress(&xb ,g_xb ); cudaGetSymbolAddress(&wdb,g_Wdb);
    cudaGetSymbolAddress(&ctxb,g_ctx); cudaGetSymbolAddress(&resp,g_res);

    cudaFuncSetAttribute(flash_k,cudaFuncAttributeMaxDynamicSharedMemorySize,FSM);

    cvt_all<<<8208,256>>>(x,Wq,Wk,Wv,Wd,mixing);                        // 0
    gemm_k<<<dim3(32,8,3),256>>>((const __nv_bfloat16*)xb,nullptr,bv,nullptr,nullptr,3); // 1
    prep8<<<12288,256>>>(x,Wcb);                                        // 2
    flash_k<<<dim3(32,HH,BB),256,FSM>>>();                              // 3 <- profiled
    gemm_k<<<dim3(32,8),256>>>((const __nv_bfloat16*)ctxb,(const __nv_bfloat16*)wdb,bd,x,resp,2); // 4
    ln_k<<<BSx,256>>>(gamma,beta,out);                                  // 5
}

// round 15
// speedup vs baseline: 1.0421x; 1.0421x over previous
#include <cuda_runtime.h>
#include <cuda_bf16.h>
#include <cuda_fp16.h>
#include <math.h>

#define BB 2
#define SS 2048
#define HH 16
#define DKx 1024
#define DVx 1024
#define BSx (BB*SS)
#define EC (0.125f*1.4426950408889634f)

__device__ __nv_bfloat16 g_xb [BSx*DKx];
__device__ __nv_bfloat16 g_Wqb[DKx*DKx];
__device__ __nv_bfloat16 g_Wkb[DKx*DKx];
__device__ __nv_bfloat16 g_Wvb[DKx*DKx];
__device__ __nv_bfloat16 g_Wdb[DKx*DKx];
__device__ __nv_bfloat16 g_mixb[HH*DKx];
__device__ __nv_bfloat16 g_q  [BSx*DKx];
__device__ __nv_bfloat16 g_k  [BSx*DKx];
__device__ __nv_bfloat16 g_v  [BSx*DVx];   // fp16 bits
__device__ unsigned char g_q8 [(size_t)HH*BSx*DKx];
__device__ unsigned char g_k8 [(size_t)BSx*DKx];
__device__ float         g_cb [BSx*HH];
__device__ __nv_bfloat16 g_ctx[BSx*DVx];
__device__ float         g_res[BSx*DVx];

static __device__ __forceinline__ unsigned sptr(const void* p){
    return (unsigned)__cvta_generic_to_shared(p);
}
static __device__ __forceinline__ void ldm4(unsigned&r0,unsigned&r1,unsigned&r2,unsigned&r3,unsigned a){
    asm volatile("ldmatrix.sync.aligned.m8n8.x4.shared.b16 {%0,%1,%2,%3},[%4];\n"
        :"=r"(r0),"=r"(r1),"=r"(r2),"=r"(r3):"r"(a));
}
static __device__ __forceinline__ void ldm4t(unsigned&r0,unsigned&r1,unsigned&r2,unsigned&r3,unsigned a){
    asm volatile("ldmatrix.sync.aligned.m8n8.x4.trans.shared.b16 {%0,%1,%2,%3},[%4];\n"
        :"=r"(r0),"=r"(r1),"=r"(r2),"=r"(r3):"r"(a));
}
static __device__ __forceinline__ void mma16816(float* c,unsigned a0,unsigned a1,unsigned a2,unsigned a3,
                                                unsigned b0,unsigned b1){
    asm volatile("mma.sync.aligned.m16n8k16.row.col.f32.bf16.bf16.f32 "
        "{%0,%1,%2,%3},{%4,%5,%6,%7},{%8,%9},{%0,%1,%2,%3};\n"
        :"+f"(c[0]),"+f"(c[1]),"+f"(c[2]),"+f"(c[3])
        :"r"(a0),"r"(a1),"r"(a2),"r"(a3),"r"(b0),"r"(b1));
}
static __device__ __forceinline__ void mma16816h(float* c,unsigned a0,unsigned a1,unsigned a2,unsigned a3,
                                                 unsigned b0,unsigned b1){
    asm volatile("mma.sync.aligned.m16n8k16.row.col.f32.f16.f16.f32 "
        "{%0,%1,%2,%3},{%4,%5,%6,%7},{%8,%9},{%0,%1,%2,%3};\n"
        :"+f"(c[0]),"+f"(c[1]),"+f"(c[2]),"+f"(c[3])
        :"r"(a0),"r"(a1),"r"(a2),"r"(a3),"r"(b0),"r"(b1));
}
static __device__ __forceinline__ void mma16832(float* c,unsigned a0,unsigned a1,unsigned a2,unsigned a3,
                                                unsigned b0,unsigned b1){
    asm volatile("mma.sync.aligned.m16n8k32.row.col.f32.e4m3.e4m3.f32 "
        "{%0,%1,%2,%3},{%4,%5,%6,%7},{%8,%9},{%0,%1,%2,%3};\n"
        :"+f"(c[0]),"+f"(c[1]),"+f"(c[2]),"+f"(c[3])
        :"r"(a0),"r"(a1),"r"(a2),"r"(a3),"r"(b0),"r"(b1));
}
static __device__ __forceinline__ unsigned pk8(float f0,float f1,float f2,float f3){
    unsigned r;
    asm("{\n\t.reg .b16 lo,hi;\n\t"
        "cvt.rn.satfinite.e4m3x2.f32 lo, %2, %1;\n\t"
        "cvt.rn.satfinite.e4m3x2.f32 hi, %4, %3;\n\t"
        "mov.b32 %0,{lo,hi};\n\t}"
        :"=r"(r):"f"(f0),"f"(f1),"f"(f2),"f"(f3));
    return r;
}
static __device__ __forceinline__ void cpa16(unsigned d,const void* s){
    asm volatile("cp.async.cg.shared.global [%0],[%1],16;"::"r"(d),"l"(s):"memory");
}
#define CPCOMMIT() asm volatile("cp.async.commit_group;":::"memory")
#define CPWAIT(n)  asm volatile("cp.async.wait_group %0;"::"n"(n):"memory")

__global__ void __launch_bounds__(256) cvt_all(const float* __restrict__ x,const float* __restrict__ wq,
        const float* __restrict__ wk,const float* __restrict__ wv,const float* __restrict__ wd,
        const float* __restrict__ mx){
    int bx=blockIdx.x; const float* s; __nv_bfloat16* d; long base;
    if(bx<4096){s=x;d=g_xb;base=bx;}
    else if(bx<5120){s=wq;d=g_Wqb;base=bx-4096;}
    else if(bx<6144){s=wk;d=g_Wkb;base=bx-5120;}
    else if(bx<7168){s=wv;d=g_Wvb;base=bx-6144;}
    else if(bx<8192){s=wd;d=g_Wdb;base=bx-7168;}
    else {s=mx;d=g_mixb;base=bx-8192;}
    size_t off=(size_t)base*1024 + threadIdx.x*4;
    float4 v=*(const float4*)(s+off);
    *(__nv_bfloat162*)(d+off)  =__floats2bfloat162_rn(v.x,v.y);
    *(__nv_bfloat162*)(d+off+2)=__floats2bfloat162_rn(v.z,v.w);
}

__global__ void __launch_bounds__(256) gemm_k(const __nv_bfloat16* __restrict__ A,
        const __nv_bfloat16* __restrict__ Bw,const float* __restrict__ bias,
        const float* __restrict__ resid,void* outp,int mode){
    __shared__ __align__(16) __nv_bfloat16 as_[128*72];
    __shared__ __align__(16) __nv_bfloat16 bs_[128*72];
    int f16o=0;
    if(mode==3){
        int z=blockIdx.z;
        Bw=(z==0)?g_Wqb:(z==1)?g_Wkb:g_Wvb;
        outp=(z==0)?(void*)g_q:(z==1)?(void*)g_k:(void*)g_v;
        if(z!=2) bias=nullptr; else f16o=1;
        mode=0;
    }
    const int m0=blockIdx.x*128,n0=blockIdx.y*128;
    const int tid=threadIdx.x,wr=tid>>5,ln=tid&31,g=ln>>2,tg=ln&3;
    const int mg=wr&3,nh=wr>>2;
    const unsigned asb=sptr(as_),bsb=sptr(bs_);
    float acc[64];
#pragma unroll
    for(int i=0;i<64;i++) acc[i]=0.f;
    for(int c0=0;c0<1024;c0+=64){
        __syncthreads();
#pragma unroll
        for(int t=0;t<4;t++){
            int idx=tid+t*256,row=idx>>3,cv=(idx&7)*8;
            *(uint4*)((char*)as_+(row*72+cv)*2)=*(const uint4*)(A +(size_t)(m0+row)*1024+c0+cv);
            *(uint4*)((char*)bs_+(row*72+cv)*2)=*(const uint4*)(Bw+(size_t)(n0+row)*1024+c0+cv);
        }
        __syncthreads();
#pragma unroll
        for(int kk=0;kk<4;kk++){
            unsigned a[2][4];
#pragma unroll
            for(int af=0;af<2;af++)
                ldm4(a[af][0],a[af][1],a[af][2],a[af][3],
                     asb+((mg*32+af*16+(ln&15))*72+kk*16+((ln>>4)<<3))*2);
#pragma unroll
            for(int nb=0;nb<4;nb++){
                unsigned b0,b1,b2,b3;
                int brow=nh*64+nb*16+(ln&7)+((ln&16)?8:0),bcol=kk*16+((ln&8)?8:0);
                ldm4(b0,b1,b2,b3,bsb+(brow*72+bcol)*2);
#pragma unroll
                for(int af=0;af<2;af++){
                    mma16816(acc+((af*4+nb)*2  )*4,a[af][0],a[af][1],a[af][2],a[af][3],b0,b1);
                    mma16816(acc+((af*4+nb)*2+1)*4,a[af][0],a[af][1],a[af][2],a[af][3],b2,b3);
                }
            }
        }
    }
#pragma unroll
    for(int af=0;af<2;af++){
        const int r0=m0+mg*32+af*16+g;
#pragma unroll
        for(int nb=0;nb<4;nb++)
#pragma unroll
        for(int p=0;p<2;p++){
            int col=n0+nh*64+nb*16+p*8+2*tg;
            float* ap=acc+((af*4+nb)*2+p)*4;
            if(mode==2){
                float* out=(float*)outp;
                float b0=bias[col],b1=bias[col+1];
                *(float2*)(out+(size_t)r0*1024+col)=make_float2(
                    ap[0]+b0+resid[(size_t)r0*1024+col],
                    ap[1]+b1+resid[(size_t)r0*1024+col+1]);
                *(float2*)(out+(size_t)(r0+8)*1024+col)=make_float2(
                    ap[2]+b0+resid[(size_t)(r0+8)*1024+col],
                    ap[3]+b1+resid[(size_t)(r0+8)*1024+col+1]);
            }else{
                __nv_bfloat16* out=(__nv_bfloat16*)outp;
                float b0=bias?bias[col]:0.f,b1=bias?bias[col+1]:0.f;
                if(f16o){
                    *(__half2*)(out+(size_t)r0*1024+col)    =__floats2half2_rn(ap[0]+b0,ap[1]+b1);
                    *(__half2*)(out+(size_t)(r0+8)*1024+col)=__floats2half2_rn(ap[2]+b0,ap[3]+b1);
                }else{
                    *(__nv_bfloat162*)(out+(size_t)r0*1024+col)    =__floats2bfloat162_rn(ap[0]+b0,ap[1]+b1);
                    *(__nv_bfloat162*)(out+(size_t)(r0+8)*1024+col)=__floats2bfloat162_rn(ap[2]+b0,ap[3]+b1);
                }
            }
        }
    }
}

__global__ void __launch_bounds__(256) prep8(const float* __restrict__ x,const float* __restrict__ Wcb){
    int bx=blockIdx.x,tid=threadIdx.x;
    if(bx<4096){
        __shared__ float xr[1024];
        int s=bx;
        for(int t=tid;t<1024;t+=256) xr[t]=x[(size_t)s*1024+t];
        __syncthreads();
        int w=tid>>5,ln=tid&31;
#pragma unroll
        for(int j=0;j<2;j++){
            int h=w*2+j;
            const float* wrow=Wcb+(size_t)h*1024;
            float sum=0.f;
            for(int c=ln;c<1024;c+=32) sum+=xr[c]*wrow[c];
#pragma unroll
            for(int off=16;off;off>>=1) sum+=__shfl_xor_sync(0xffffffffu,sum,off);
            if(ln==0) g_cb[(size_t)s*HH+h]=sum;
        }
    }else if(bx<8192){
        int row=bx-4096, col=tid*4;
        const __nv_bfloat162* q2=(const __nv_bfloat162*)(g_q+(size_t)row*1024+col);
        float2 q0=__bfloat1622float2(q2[0]),q1=__bfloat1622float2(q2[1]);
#pragma unroll
        for(int h=0;h<HH;h++){
            const __nv_bfloat162* m2=(const __nv_bfloat162*)(g_mixb+(size_t)h*1024+col);
            float2 m0=__bfloat1622float2(m2[0]),m1=__bfloat1622float2(m2[1]);
            unsigned p=pk8(q0.x*m0.x,q0.y*m0.y,q1.x*m1.x,q1.y*m1.y);
            *(unsigned*)(g_q8+((size_t)h*4096+row)*1024+col)=p;
        }
    }else{
        size_t off=((size_t)(bx-8192)*256+tid)*4;
        const __nv_bfloat162* k2=(const __nv_bfloat162*)(g_k+off);
        float2 k0=__bfloat1622float2(k2[0]),k1=__bfloat1622float2(k2[1]);
        *(unsigned*)(g_k8+off)=pk8(k0.x,k0.y,k1.x,k1.y);
    }
}

// ---------- FP8 flash, 4-stage ring, one chunk/barrier, issue-at-top ----------
#define STG  15360u
#define OVS  61440u
#define OPS  79872u
#define OCBS 97280u
#define ORL  97792u
#define FSM  98816

__global__ void __launch_bounds__(256,2) flash_k(){
    extern __shared__ __align__(16) char sm[];
    const int b=blockIdx.z,h=blockIdx.y,i0=blockIdx.x*64;
    const int tid=threadIdx.x,wr=tid>>5,ln=tid&31,g=ln>>2,tg=ln&3;
    const int mg=wr&1,ng=wr>>1;      // score: 32 rows x 32 keys
    const int pmg=wr&3,pnh=wr>>2;    // PV: 16 rows x 32 vcols
    const unsigned sb=sptr(sm);
    float* cbs=(float*)(sm+OCBS);
    float* rlP=(float*)(sm+ORL);
    const unsigned char* q8g=g_q8+((size_t)h*4096+b*2048+i0)*1024;
    const unsigned char* k8g=g_k8+(size_t)(b*2048)*1024;
    const __nv_bfloat16* vg=g_v+(size_t)(b*SS)*DVx;

    const unsigned char* qsrc=q8g+(size_t)(tid>>2)*1024+(tid&3)*16;
    const unsigned  qdst=sb+(unsigned)((tid>>2)*80+(tid&3)*16);
    const unsigned char* ksrc=k8g+(size_t)(tid>>2)*1024+(tid&3)*16;
    const unsigned  kdst=sb+5120u+(unsigned)((tid>>2)*80+(tid&3)*16);
    const __nv_bfloat16* vsrc=vg+(size_t)(tid>>3)*1024+(size_t)h*64+(tid&7)*8;
    const unsigned  vdst=sb+OVS+(unsigned)(((tid>>3)*72+(tid&7)*8)*2);
    const unsigned qoff=(unsigned)((mg*32+(ln&15))*80+((ln>>4)<<4));
    const unsigned koff=5120u+(unsigned)((ng*32+(ln&7)+((ln&16)?8:0))*80+((ln&8)?16:0));
    const unsigned poff=sb+OPS+(unsigned)(((pmg*16+(ln&15))*136+((ln>>4)<<3))*2);
    const unsigned voff=sb+OVS+(unsigned)((((ln&7)+((ln&8)?8:0))*72+pnh*32+((ln&16)?8:0))*2);

    float sacc[32],octx[16];
    float lsA[2][2]={{0.f,0.f},{0.f,0.f}};
#pragma unroll
    for(int i=0;i<16;i++) octx[i]=0.f;

    auto issue=[&](unsigned stg,int c0,int j0){
        cpa16(qdst+stg*STG, qsrc+c0);
        cpa16(kdst+stg*STG,       ksrc+(size_t)j0*1024+c0);
        cpa16(kdst+stg*STG+5120u, ksrc+(size_t)(j0+64)*1024+c0);
    };
    auto issueV=[&](int j0){
#pragma unroll
        for(int t=0;t<4;t++)
            cpa16(vdst+(unsigned)(t*32*72*2), vsrc+(size_t)(j0+t*32)*1024);
    };

    issue(0,0,0);   CPCOMMIT();
    issue(1,64,0);  CPCOMMIT();
    issue(2,128,0); CPCOMMIT();

    for(int jt=0;jt<16;jt++){
        const int j0=jt*128;
#pragma unroll
        for(int i=0;i<32;i++) sacc[i]=0.f;
#pragma unroll
        for(int c=0;c<16;c++){
            if(c<14){ CPWAIT(2); }
            else if(c==14){ if(__builtin_expect(jt==15,0)) CPWAIT(1); else CPWAIT(2); }
            else { if(__builtin_expect(jt==15,0)) CPWAIT(0); else CPWAIT(2); }
            __syncthreads();
            if(c==0&&tid<128) cbs[tid]=g_cb[(size_t)(b*SS+j0+tid)*HH+h]*EC;
            // issue-at-top: refill stage (c+3)&3 = (c-1)&3, consumed at c-1 (safe post-barrier)
            if(c<12){ issue((c+3)&3,(c+3)*64,j0); CPCOMMIT(); }
            else if(c==12){ issue(3,960,j0); issueV(j0); CPCOMMIT(); }
            else if(jt<15){ issue((c+3)&3,(c-13)*64,j0+128); CPCOMMIT(); }
            const unsigned base=sb+(unsigned)((c&3)*STG);
#pragma unroll
            for(int kk=0;kk<2;kk++){
                unsigned a[2][4],bq[2][4];
#pragma unroll
                for(int rf=0;rf<2;rf++)
                    ldm4(a[rf][0],a[rf][1],a[rf][2],a[rf][3],base+qoff+rf*1280u+kk*32);
#pragma unroll
                for(int kf=0;kf<2;kf++)
                    ldm4(bq[kf][0],bq[kf][1],bq[kf][2],bq[kf][3],base+koff+kf*1280u+kk*32);
#pragma unroll
                for(int rf=0;rf<2;rf++)
#pragma unroll
                for(int kf=0;kf<2;kf++){
                    mma16832(sacc+(rf*4+kf*2  )*4,a[rf][0],a[rf][1],a[rf][2],a[rf][3],bq[kf][0],bq[kf][1]);
                    mma16832(sacc+(rf*4+kf*2+1)*4,a[rf][0],a[rf][1],a[rf][2],a[rf][3],bq[kf][2],bq[kf][3]);
                }
            }
        }
        // fp16 softmax epilogue
        {
#pragma unroll
            for(int rf=0;rf<2;rf++){
                int r0=mg*32+rf*16+g;
                unsigned hs0=0,hs1=0;
#pragma unroll
                for(int kf=0;kf<2;kf++)
#pragma unroll
                for(int nf=0;nf<2;nf++){
                    float* sp=sacc+(rf*4+kf*2+nf)*4;
                    int col=ng*32+kf*16+nf*8+2*tg;
                    float c0v=cbs[col],c1v=cbs[col+1];
                    float s0=fmaf(sp[0],EC,c0v),s1=fmaf(sp[1],EC,c1v);
                    float s2=fmaf(sp[2],EC,c0v),s3=fmaf(sp[3],EC,c1v);
                    unsigned u0,u1,p0,p1;
                    asm("cvt.rn.f16x2.f32 %0,%1,%2;":"=r"(u0):"f"(s1),"f"(s0));
                    asm("cvt.rn.f16x2.f32 %0,%1,%2;":"=r"(u1):"f"(s3),"f"(s2));
                    asm("ex2.approx.f16x2 %0,%1;":"=r"(p0):"r"(u0));
                    asm("ex2.approx.f16x2 %0,%1;":"=r"(p1):"r"(u1));
                    asm("add.rn.f16x2 %0,%1,%2;":"=r"(hs0):"r"(hs0),"r"(p0));
                    asm("add.rn.f16x2 %0,%1,%2;":"=r"(hs1):"r"(hs1),"r"(p1));
                    *(unsigned*)(sm+OPS+((size_t)r0*136+col)*2)    =p0;
                    *(unsigned*)(sm+OPS+((size_t)(r0+8)*136+col)*2)=p1;
                }
                float2 f0=__half22float2(*(__half2*)&hs0);
                float2 f1=__half22float2(*(__half2*)&hs1);
                lsA[rf][0]+=f0.x+f0.y; lsA[rf][1]+=f1.x+f1.y;
            }
        }
        __syncthreads();   // P complete; V arrived with c==12 group
#pragma unroll
        for(int kb2=0;kb2<8;kb2++){
            unsigned p0,p1,p2,p3;
            ldm4(p0,p1,p2,p3,poff+(unsigned)(kb2*32));
#pragma unroll
            for(int vp=0;vp<2;vp++){
                unsigned b0,b1,b2,b3;
                ldm4t(b0,b1,b2,b3,voff+(unsigned)((kb2*16*72+vp*16)*2));
                mma16816h(octx+(2*vp  )*4,p0,p1,p2,p3,b0,b1);
                mma16816h(octx+(2*vp+1)*4,p0,p1,p2,p3,b2,b3);
            }
        }
    }
#pragma unroll
    for(int rf=0;rf<2;rf++)
#pragma unroll
    for(int hf=0;hf<2;hf++){
        float v=lsA[rf][hf];
        v+=__shfl_xor_sync(0xffffffffu,v,1);
        v+=__shfl_xor_sync(0xffffffffu,v,2);
        if(tg==0) rlP[ng*64+mg*32+rf*16+hf*8+g]=v;
    }
    __syncthreads();
    int rr=pmg*16+g;
    float inv0=1.f/(rlP[rr]  +rlP[64+rr]  +rlP[128+rr]  +rlP[192+rr]);
    float inv1=1.f/(rlP[rr+8]+rlP[64+rr+8]+rlP[128+rr+8]+rlP[192+rr+8]);
    int r0=i0+rr;
    __nv_bfloat16* cg=g_ctx+(size_t)(b*SS)*DVx+h*64;
#pragma unroll
    for(int i=0;i<4;i++){
        int col=pnh*32+i*8+2*tg;
        *(__nv_bfloat162*)(cg+(size_t)r0*DVx+col)=
            __floats2bfloat162_rn(octx[i*4+0]*inv0,octx[i*4+1]*inv0);
        *(__nv_bfloat162*)(cg+(size_t)(r0+8)*DVx+col)=
            __floats2bfloat162_rn(octx[i*4+2]*inv1,octx[i*4+3]*inv1);
    }
}

__global__ void __launch_bounds__(256) ln_k(const float* __restrict__ gamma,
        const float* __restrict__ beta,float* __restrict__ out){
    int s=blockIdx.x,tid=threadIdx.x;
    const float* r=g_res+(size_t)s*1024;
    float sum=0.f,sq=0.f;
#pragma unroll
    for(int i=tid;i<1024;i+=256){ float v=r[i]; sum+=v; sq+=v*v; }
#pragma unroll
    for(int off=16;off;off>>=1){
        sum+=__shfl_xor_sync(0xffffffffu,sum,off);
        sq +=__shfl_xor_sync(0xffffffffu,sq ,off);
    }
    __shared__ float ss[8],sv[8];
    if((tid&31)==0){ ss[tid>>5]=sum; sv[tid>>5]=sq; }
    __syncthreads();
    float tot=0.f,tot2=0.f;
#pragma unroll
    for(int i=0;i<8;i++){ tot+=ss[i]; tot2+=sv[i]; }
    float mu=tot*(1.f/1024.f),var=tot2*(1.f/1024.f)-mu*mu;
    float is=rsqrtf(var+1e-5f);
    for(int i=tid;i<1024;i+=256)
        out[(size_t)s*1024+i]=(r[i]-mu)*is*gamma[i]+beta[i];
}

extern "C" void kernel_launch(void* const* d_in,const int* in_sizes,int n_in,
                              void* d_out,int out_size){
    const float* x    =(const float*)d_in[0];
    const float* Wq   =(const float*)d_in[1];
    const float* Wk   =(const float*)d_in[2];
    const float* Wcb  =(const float*)d_in[3];
    const float* Wv   =(const float*)d_in[4];
    const float* bv   =(const float*)d_in[5];
    const float* mixing=(const float*)d_in[6];
    const float* Wd   =(const float*)d_in[7];
    const float* bd   =(const float*)d_in[8];
    const float* gamma=(const float*)d_in[9];
    const float* beta =(const float*)d_in[10];
    float* out=(float*)d_out;

    void *xb,*wdb,*ctxb,*resp;
    cudaGetSymbolAddress(&xb ,g_xb ); cudaGetSymbolAddress(&wdb,g_Wdb);
    cudaGetSymbolAddress(&ctxb,g_ctx); cudaGetSymbolAddress(&resp,g_res);

    cudaFuncSetAttribute(flash_k,cudaFuncAttributeMaxDynamicSharedMemorySize,FSM);

    cvt_all<<<8208,256>>>(x,Wq,Wk,Wv,Wd,mixing);                        // 0
    gemm_k<<<dim3(32,8,3),256>>>((const __nv_bfloat16*)xb,nullptr,bv,nullptr,nullptr,3); // 1
    prep8<<<12288,256>>>(x,Wcb);                                        // 2
    flash_k<<<dim3(32,HH,BB),256,FSM>>>();                              // 3 <- profiled
    gemm_k<<<dim3(32,8),256>>>((const __nv_bfloat16*)ctxb,(const __nv_bfloat16*)wdb,bd,x,resp,2); // 4
    ln_k<<<BSx,256>>>(gamma,beta,out);                                  // 5
}

// round 16
// speedup vs baseline: 1.0793x; 1.0356x over previous
#include <cuda_runtime.h>
#include <cuda_bf16.h>
#include <cuda_fp16.h>
#include <math.h>

#define BB 2
#define SS 2048
#define HH 16
#define DKx 1024
#define DVx 1024
#define BSx (BB*SS)
#define EC (0.125f*1.4426950408889634f)

__device__ __nv_bfloat16 g_xb [BSx*DKx];
__device__ __nv_bfloat16 g_Wqb[DKx*DKx];
__device__ __nv_bfloat16 g_Wkb[DKx*DKx];
__device__ __nv_bfloat16 g_Wvb[DKx*DKx];
__device__ __nv_bfloat16 g_Wdb[DKx*DKx];
__device__ __nv_bfloat16 g_mixb[HH*DKx];
__device__ __nv_bfloat16 g_q  [BSx*DKx];
__device__ __nv_bfloat16 g_k  [BSx*DKx];
__device__ __nv_bfloat16 g_v  [BSx*DVx];   // fp16 bits
__device__ unsigned char g_q8 [(size_t)HH*BSx*DKx];
__device__ unsigned char g_k8 [(size_t)BSx*DKx];
__device__ float         g_cb [BSx*HH];
__device__ __nv_bfloat16 g_ctx[BSx*DVx];
__device__ float         g_res[BSx*DVx];

static __device__ __forceinline__ unsigned sptr(const void* p){
    return (unsigned)__cvta_generic_to_shared(p);
}
static __device__ __forceinline__ void ldm4(unsigned&r0,unsigned&r1,unsigned&r2,unsigned&r3,unsigned a){
    asm volatile("ldmatrix.sync.aligned.m8n8.x4.shared.b16 {%0,%1,%2,%3},[%4];\n"
        :"=r"(r0),"=r"(r1),"=r"(r2),"=r"(r3):"r"(a));
}
static __device__ __forceinline__ void ldm4t(unsigned&r0,unsigned&r1,unsigned&r2,unsigned&r3,unsigned a){
    asm volatile("ldmatrix.sync.aligned.m8n8.x4.trans.shared.b16 {%0,%1,%2,%3},[%4];\n"
        :"=r"(r0),"=r"(r1),"=r"(r2),"=r"(r3):"r"(a));
}
static __device__ __forceinline__ void mma16816(float* c,unsigned a0,unsigned a1,unsigned a2,unsigned a3,
                                                unsigned b0,unsigned b1){
    asm volatile("mma.sync.aligned.m16n8k16.row.col.f32.bf16.bf16.f32 "
        "{%0,%1,%2,%3},{%4,%5,%6,%7},{%8,%9},{%0,%1,%2,%3};\n"
        :"+f"(c[0]),"+f"(c[1]),"+f"(c[2]),"+f"(c[3])
        :"r"(a0),"r"(a1),"r"(a2),"r"(a3),"r"(b0),"r"(b1));
}
static __device__ __forceinline__ void mma16816h(float* c,unsigned a0,unsigned a1,unsigned a2,unsigned a3,
                                                 unsigned b0,unsigned b1){
    asm volatile("mma.sync.aligned.m16n8k16.row.col.f32.f16.f16.f32 "
        "{%0,%1,%2,%3},{%4,%5,%6,%7},{%8,%9},{%0,%1,%2,%3};\n"
        :"+f"(c[0]),"+f"(c[1]),"+f"(c[2]),"+f"(c[3])
        :"r"(a0),"r"(a1),"r"(a2),"r"(a3),"r"(b0),"r"(b1));
}
static __device__ __forceinline__ void mma16832(float* c,unsigned a0,unsigned a1,unsigned a2,unsigned a3,
                                                unsigned b0,unsigned b1){
    asm volatile("mma.sync.aligned.m16n8k32.row.col.f32.e4m3.e4m3.f32 "
        "{%0,%1,%2,%3},{%4,%5,%6,%7},{%8,%9},{%0,%1,%2,%3};\n"
        :"+f"(c[0]),"+f"(c[1]),"+f"(c[2]),"+f"(c[3])
        :"r"(a0),"r"(a1),"r"(a2),"r"(a3),"r"(b0),"r"(b1));
}
static __device__ __forceinline__ unsigned pk8(float f0,float f1,float f2,float f3){
    unsigned r;
    asm("{\n\t.reg .b16 lo,hi;\n\t"
        "cvt.rn.satfinite.e4m3x2.f32 lo, %2, %1;\n\t"
        "cvt.rn.satfinite.e4m3x2.f32 hi, %4, %3;\n\t"
        "mov.b32 %0,{lo,hi};\n\t}"
        :"=r"(r):"f"(f0),"f"(f1),"f"(f2),"f"(f3));
    return r;
}
static __device__ __forceinline__ void cpa16(unsigned d,const void* s){
    asm volatile("cp.async.cg.shared.global [%0],[%1],16;"::"r"(d),"l"(s):"memory");
}
#define CPCOMMIT() asm volatile("cp.async.commit_group;":::"memory")
#define CPWAIT(n)  asm volatile("cp.async.wait_group %0;"::"n"(n):"memory")

__global__ void __launch_bounds__(256) cvt_all(const float* __restrict__ x,const float* __restrict__ wq,
        const float* __restrict__ wk,const float* __restrict__ wv,const float* __restrict__ wd,
        const float* __restrict__ mx){
    int bx=blockIdx.x; const float* s; __nv_bfloat16* d; long base;
    if(bx<4096){s=x;d=g_xb;base=bx;}
    else if(bx<5120){s=wq;d=g_Wqb;base=bx-4096;}
    else if(bx<6144){s=wk;d=g_Wkb;base=bx-5120;}
    else if(bx<7168){s=wv;d=g_Wvb;base=bx-6144;}
    else if(bx<8192){s=wd;d=g_Wdb;base=bx-7168;}
    else {s=mx;d=g_mixb;base=bx-8192;}
    size_t off=(size_t)base*1024 + threadIdx.x*4;
    float4 v=*(const float4*)(s+off);
    *(__nv_bfloat162*)(d+off)  =__floats2bfloat162_rn(v.x,v.y);
    *(__nv_bfloat162*)(d+off+2)=__floats2bfloat162_rn(v.z,v.w);
}

// ---------- bf16 GEMM, cp.async 2-stage pipeline, 32x64 warp tiles ----------
#define GSTG 18432u
#define GSM  73728

__global__ void __launch_bounds__(256) gemm_k(const __nv_bfloat16* __restrict__ A,
        const __nv_bfloat16* __restrict__ Bw,const float* __restrict__ bias,
        const float* __restrict__ resid,void* outp,int mode){
    extern __shared__ __align__(16) char gsm[];
    const unsigned gb=sptr(gsm);
    int f16o=0;
    if(mode==3){
        int z=blockIdx.z;
        Bw=(z==0)?g_Wqb:(z==1)?g_Wkb:g_Wvb;
        outp=(z==0)?(void*)g_q:(z==1)?(void*)g_k:(void*)g_v;
        if(z!=2) bias=nullptr; else f16o=1;
        mode=0;
    }
    const int m0=blockIdx.x*128,n0=blockIdx.y*128;
    const int tid=threadIdx.x,wr=tid>>5,ln=tid&31,g=ln>>2,tg=ln&3;
    const int mg=wr&3,nh=wr>>2;
    float acc[64];
#pragma unroll
    for(int i=0;i<64;i++) acc[i]=0.f;
    auto gissue=[&](int p,int c0){
#pragma unroll
        for(int t=0;t<4;t++){
            int idx=t*256+tid,row=idx>>3,cv=(idx&7)*8;
            cpa16(gb+(unsigned)p*GSTG+(unsigned)((row*72+cv)*2),
                  A +(size_t)(m0+row)*1024+c0+cv);
            cpa16(gb+2u*GSTG+(unsigned)p*GSTG+(unsigned)((row*72+cv)*2),
                  Bw+(size_t)(n0+row)*1024+c0+cv);
        }
        CPCOMMIT();
    };
    gissue(0,0);
    for(int c=0;c<16;c++){
        if(c<15){ gissue((c+1)&1,(c+1)*64); CPWAIT(1); }
        else CPWAIT(0);
        __syncthreads();
        const unsigned asb=gb+(unsigned)((c&1)*GSTG);
        const unsigned bsb=gb+2u*GSTG+(unsigned)((c&1)*GSTG);
#pragma unroll
        for(int kk=0;kk<4;kk++){
            unsigned a[2][4];
#pragma unroll
            for(int af=0;af<2;af++)
                ldm4(a[af][0],a[af][1],a[af][2],a[af][3],
                     asb+((mg*32+af*16+(ln&15))*72+kk*16+((ln>>4)<<3))*2);
#pragma unroll
            for(int nb=0;nb<4;nb++){
                unsigned b0,b1,b2,b3;
                int brow=nh*64+nb*16+(ln&7)+((ln&16)?8:0),bcol=kk*16+((ln&8)?8:0);
                ldm4(b0,b1,b2,b3,bsb+(brow*72+bcol)*2);
#pragma unroll
                for(int af=0;af<2;af++){
                    mma16816(acc+((af*4+nb)*2  )*4,a[af][0],a[af][1],a[af][2],a[af][3],b0,b1);
                    mma16816(acc+((af*4+nb)*2+1)*4,a[af][0],a[af][1],a[af][2],a[af][3],b2,b3);
                }
            }
        }
        __syncthreads();
    }
#pragma unroll
    for(int af=0;af<2;af++){
        const int r0=m0+mg*32+af*16+g;
#pragma unroll
        for(int nb=0;nb<4;nb++)
#pragma unroll
        for(int p=0;p<2;p++){
            int col=n0+nh*64+nb*16+p*8+2*tg;
            float* ap=acc+((af*4+nb)*2+p)*4;
            if(mode==2){
                float* out=(float*)outp;
                float b0=bias[col],b1=bias[col+1];
                *(float2*)(out+(size_t)r0*1024+col)=make_float2(
                    ap[0]+b0+resid[(size_t)r0*1024+col],
                    ap[1]+b1+resid[(size_t)r0*1024+col+1]);
                *(float2*)(out+(size_t)(r0+8)*1024+col)=make_float2(
                    ap[2]+b0+resid[(size_t)(r0+8)*1024+col],
                    ap[3]+b1+resid[(size_t)(r0+8)*1024+col+1]);
            }else{
                __nv_bfloat16* out=(__nv_bfloat16*)outp;
                float b0=bias?bias[col]:0.f,b1=bias?bias[col+1]:0.f;
                if(f16o){
                    *(__half2*)(out+(size_t)r0*1024+col)    =__floats2half2_rn(ap[0]+b0,ap[1]+b1);
                    *(__half2*)(out+(size_t)(r0+8)*1024+col)=__floats2half2_rn(ap[2]+b0,ap[3]+b1);
                }else{
                    *(__nv_bfloat162*)(out+(size_t)r0*1024+col)    =__floats2bfloat162_rn(ap[0]+b0,ap[1]+b1);
                    *(__nv_bfloat162*)(out+(size_t)(r0+8)*1024+col)=__floats2bfloat162_rn(ap[2]+b0,ap[3]+b1);
                }
            }
        }
    }
}

__global__ void __launch_bounds__(256) prep8(const float* __restrict__ x,const float* __restrict__ Wcb){
    int bx=blockIdx.x,tid=threadIdx.x;
    if(bx<4096){
        __shared__ float xr[1024];
        int s=bx;
        for(int t=tid;t<1024;t+=256) xr[t]=x[(size_t)s*1024+t];
        __syncthreads();
        int w=tid>>5,ln=tid&31;
#pragma unroll
        for(int j=0;j<2;j++){
            int h=w*2+j;
            const float* wrow=Wcb+(size_t)h*1024;
            float sum=0.f;
            for(int c=ln;c<1024;c+=32) sum+=xr[c]*wrow[c];
#pragma unroll
            for(int off=16;off;off>>=1) sum+=__shfl_xor_sync(0xffffffffu,sum,off);
            if(ln==0) g_cb[(size_t)s*HH+h]=sum;
        }
    }else if(bx<8192){
        int row=bx-4096, col=tid*4;
        const __nv_bfloat162* q2=(const __nv_bfloat162*)(g_q+(size_t)row*1024+col);
        float2 q0=__bfloat1622float2(q2[0]),q1=__bfloat1622float2(q2[1]);
#pragma unroll
        for(int h=0;h<HH;h++){
            const __nv_bfloat162* m2=(const __nv_bfloat162*)(g_mixb+(size_t)h*1024+col);
            float2 m0=__bfloat1622float2(m2[0]),m1=__bfloat1622float2(m2[1]);
            unsigned p=pk8(q0.x*m0.x,q0.y*m0.y,q1.x*m1.x,q1.y*m1.y);
            *(unsigned*)(g_q8+((size_t)h*4096+row)*1024+col)=p;
        }
    }else{
        size_t off=((size_t)(bx-8192)*256+tid)*4;
        const __nv_bfloat162* k2=(const __nv_bfloat162*)(g_k+off);
        float2 k0=__bfloat1622float2(k2[0]),k1=__bfloat1622float2(k2[1]);
        *(unsigned*)(g_k8+off)=pk8(k0.x,k0.y,k1.x,k1.y);
    }
}

// ---------- FP8 flash: R13 verbatim (4-stage ring, issue-after-score) ----------
#define STG  15360u
#define OVS  61440u
#define OPS  79872u
#define OCBS 97280u
#define ORL  97792u
#define FSM  98816

__global__ void __launch_bounds__(256,2) flash_k(){
    extern __shared__ __align__(16) char sm[];
    const int b=blockIdx.z,h=blockIdx.y,i0=blockIdx.x*64;
    const int tid=threadIdx.x,wr=tid>>5,ln=tid&31,g=ln>>2,tg=ln&3;
    const int mg=wr&1,ng=wr>>1;      // score: 32 rows x 32 keys
    const int pmg=wr&3,pnh=wr>>2;    // PV: 16 rows x 32 vcols
    const unsigned sb=sptr(sm);
    float* cbs=(float*)(sm+OCBS);
    float* rlP=(float*)(sm+ORL);
    const unsigned char* q8g=g_q8+((size_t)h*4096+b*2048+i0)*1024;
    const unsigned char* k8g=g_k8+(size_t)(b*2048)*1024;
    const __nv_bfloat16* vg=g_v+(size_t)(b*SS)*DVx;

    const unsigned char* qsrc=q8g+(size_t)(tid>>2)*1024+(tid&3)*16;
    const unsigned  qdst=sb+(unsigned)((tid>>2)*80+(tid&3)*16);
    const unsigned char* ksrc=k8g+(size_t)(tid>>2)*1024+(tid&3)*16;
    const unsigned  kdst=sb+5120u+(unsigned)((tid>>2)*80+(tid&3)*16);
    const __nv_bfloat16* vsrc=vg+(size_t)(tid>>3)*1024+(size_t)h*64+(tid&7)*8;
    const unsigned  vdst=sb+OVS+(unsigned)(((tid>>3)*72+(tid&7)*8)*2);
    const unsigned qoff=(unsigned)((mg*32+(ln&15))*80+((ln>>4)<<4));
    const unsigned koff=5120u+(unsigned)((ng*32+(ln&7)+((ln&16)?8:0))*80+((ln&8)?16:0));
    const unsigned poff=sb+OPS+(unsigned)(((pmg*16+(ln&15))*136+((ln>>4)<<3))*2);
    const unsigned voff=sb+OVS+(unsigned)((((ln&7)+((ln&8)?8:0))*72+pnh*32+((ln&16)?8:0))*2);

    float sacc[32],octx[16];
    float lsA[2][2]={{0.f,0.f},{0.f,0.f}};
#pragma unroll
    for(int i=0;i<16;i++) octx[i]=0.f;

    auto issue=[&](unsigned stg,int c0,int j0){
        cpa16(qdst+stg*STG, qsrc+c0);
        cpa16(kdst+stg*STG,       ksrc+(size_t)j0*1024+c0);
        cpa16(kdst+stg*STG+5120u, ksrc+(size_t)(j0+64)*1024+c0);
    };
    auto issueV=[&](int j0){
#pragma unroll
        for(int t=0;t<4;t++)
            cpa16(vdst+(unsigned)(t*32*72*2), vsrc+(size_t)(j0+t*32)*1024);
    };

    issue(0,0,0);   CPCOMMIT();
    issue(1,64,0);  CPCOMMIT();
    issue(2,128,0); CPCOMMIT();

    for(int jt=0;jt<16;jt++){
        const int j0=jt*128;
#pragma unroll
        for(int i=0;i<32;i++) sacc[i]=0.f;
#pragma unroll
        for(int c=0;c<16;c++){
            if(c<14){ CPWAIT(2); }
            else if(c==14){ if(__builtin_expect(jt==15,0)) CPWAIT(1); else CPWAIT(2); }
            else { if(__builtin_expect(jt==15,0)) CPWAIT(0); else CPWAIT(2); }
            __syncthreads();
            if(c==0&&tid<128) cbs[tid]=g_cb[(size_t)(b*SS+j0+tid)*HH+h]*EC;
            const unsigned base=sb+(unsigned)((c&3)*STG);
#pragma unroll
            for(int kk=0;kk<2;kk++){
                unsigned a[2][4],bq[2][4];
#pragma unroll
                for(int rf=0;rf<2;rf++)
                    ldm4(a[rf][0],a[rf][1],a[rf][2],a[rf][3],base+qoff+rf*1280u+kk*32);
#pragma unroll
                for(int kf=0;kf<2;kf++)
                    ldm4(bq[kf][0],bq[kf][1],bq[kf][2],bq[kf][3],base+koff+kf*1280u+kk*32);
#pragma unroll
                for(int rf=0;rf<2;rf++)
#pragma unroll
                for(int kf=0;kf<2;kf++){
                    mma16832(sacc+(rf*4+kf*2  )*4,a[rf][0],a[rf][1],a[rf][2],a[rf][3],bq[kf][0],bq[kf][1]);
                    mma16832(sacc+(rf*4+kf*2+1)*4,a[rf][0],a[rf][1],a[rf][2],a[rf][3],bq[kf][2],bq[kf][3]);
                }
            }
            if(c<12){ issue((c+3)&3,(c+3)*64,j0); CPCOMMIT(); }
            else if(c==12){ issue(3,960,j0); issueV(j0); CPCOMMIT(); }
            else if(jt<15){ issue((c+3)&3,(c-13)*64,j0+128); CPCOMMIT(); }
        }
        {
#pragma unroll
            for(int rf=0;rf<2;rf++){
                int r0=mg*32+rf*16+g;
                unsigned hs0=0,hs1=0;
#pragma unroll
                for(int kf=0;kf<2;kf++)
#pragma unroll
                for(int nf=0;nf<2;nf++){
                    float* sp=sacc+(rf*4+kf*2+nf)*4;
                    int col=ng*32+kf*16+nf*8+2*tg;
                    float c0v=cbs[col],c1v=cbs[col+1];
                    float s0=fmaf(sp[0],EC,c0v),s1=fmaf(sp[1],EC,c1v);
                    float s2=fmaf(sp[2],EC,c0v),s3=fmaf(sp[3],EC,c1v);
                    unsigned u0,u1,p0,p1;
                    asm("cvt.rn.f16x2.f32 %0,%1,%2;":"=r"(u0):"f"(s1),"f"(s0));
                    asm("cvt.rn.f16x2.f32 %0,%1,%2;":"=r"(u1):"f"(s3),"f"(s2));
                    asm("ex2.approx.f16x2 %0,%1;":"=r"(p0):"r"(u0));
                    asm("ex2.approx.f16x2 %0,%1;":"=r"(p1):"r"(u1));
                    asm("add.rn.f16x2 %0,%1,%2;":"=r"(hs0):"r"(hs0),"r"(p0));
                    asm("add.rn.f16x2 %0,%1,%2;":"=r"(hs1):"r"(hs1),"r"(p1));
                    *(unsigned*)(sm+OPS+((size_t)r0*136+col)*2)    =p0;
                    *(unsigned*)(sm+OPS+((size_t)(r0+8)*136+col)*2)=p1;
                }
                float2 f0=__half22float2(*(__half2*)&hs0);
                float2 f1=__half22float2(*(__half2*)&hs1);
                lsA[rf][0]+=f0.x+f0.y; lsA[rf][1]+=f1.x+f1.y;
            }
        }
        __syncthreads();
#pragma unroll
        for(int kb2=0;kb2<8;kb2++){
            unsigned p0,p1,p2,p3;
            ldm4(p0,p1,p2,p3,poff+(unsigned)(kb2*32));
#pragma unroll
            for(int vp=0;vp<2;vp++){
                unsigned b0,b1,b2,b3;
                ldm4t(b0,b1,b2,b3,voff+(unsigned)((kb2*16*72+vp*16)*2));
                mma16816h(octx+(2*vp  )*4,p0,p1,p2,p3,b0,b1);
                mma16816h(octx+(2*vp+1)*4,p0,p1,p2,p3,b2,b3);
            }
        }
    }
#pragma unroll
    for(int rf=0;rf<2;rf++)
#pragma unroll
    for(int hf=0;hf<2;hf++){
        float v=lsA[rf][hf];
        v+=__shfl_xor_sync(0xffffffffu,v,1);
        v+=__shfl_xor_sync(0xffffffffu,v,2);
        if(tg==0) rlP[ng*64+mg*32+rf*16+hf*8+g]=v;
    }
    __syncthreads();
    int rr=pmg*16+g;
    float inv0=1.f/(rlP[rr]  +rlP[64+rr]  +rlP[128+rr]  +rlP[192+rr]);
    float inv1=1.f/(rlP[rr+8]+rlP[64+rr+8]+rlP[128+rr+8]+rlP[192+rr+8]);
    int r0=i0+rr;
    __nv_bfloat16* cg=g_ctx+(size_t)(b*SS)*DVx+h*64;
#pragma unroll
    for(int i=0;i<4;i++){
        int col=pnh*32+i*8+2*tg;
        *(__nv_bfloat162*)(cg+(size_t)r0*DVx+col)=
            __floats2bfloat162_rn(octx[i*4+0]*inv0,octx[i*4+1]*inv0);
        *(__nv_bfloat162*)(cg+(size_t)(r0+8)*DVx+col)=
            __floats2bfloat162_rn(octx[i*4+2]*inv1,octx[i*4+3]*inv1);
    }
}

__global__ void __launch_bounds__(256) ln_k(const float* __restrict__ gamma,
        const float* __restrict__ beta,float* __restrict__ out){
    int s=blockIdx.x,tid=threadIdx.x;
    const float* r=g_res+(size_t)s*1024;
    float sum=0.f,sq=0.f;
#pragma unroll
    for(int i=tid;i<1024;i+=256){ float v=r[i]; sum+=v; sq+=v*v; }
#pragma unroll
    for(int off=16;off;off>>=1){
        sum+=__shfl_xor_sync(0xffffffffu,sum,off);
        sq +=__shfl_xor_sync(0xffffffffu,sq ,off);
    }
    __shared__ float ss[8],sv[8];
    if((tid&31)==0){ ss[tid>>5]=sum; sv[tid>>5]=sq; }
    __syncthreads();
    float tot=0.f,tot2=0.f;
#pragma unroll
    for(int i=0;i<8;i++){ tot+=ss[i]; tot2+=sv[i]; }
    float mu=tot*(1.f/1024.f),var=tot2*(1.f/1024.f)-mu*mu;
    float is=rsqrtf(var+1e-5f);
    for(int i=tid;i<1024;i+=256)
        out[(size_t)s*1024+i]=(r[i]-mu)*is*gamma[i]+beta[i];
}

extern "C" void kernel_launch(void* const* d_in,const int* in_sizes,int n_in,
                              void* d_out,int out_size){
    const float* x    =(const float*)d_in[0];
    const float* Wq   =(const float*)d_in[1];
    const float* Wk   =(const float*)d_in[2];
    const float* Wcb  =(const float*)d_in[3];
    const float* Wv   =(const float*)d_in[4];
    const float* bv   =(const float*)d_in[5];
    const float* mixing=(const float*)d_in[6];
    const float* Wd   =(const float*)d_in[7];
    const float* bd   =(const float*)d_in[8];
    const float* gamma=(const float*)d_in[9];
    const float* beta =(const float*)d_in[10];
    float* out=(float*)d_out;

    void *xb,*wdb,*ctxb,*resp;
    cudaGetSymbolAddress(&xb ,g_xb ); cudaGetSymbolAddress(&wdb,g_Wdb);
    cudaGetSymbolAddress(&ctxb,g_ctx); cudaGetSymbolAddress(&resp,g_res);

    cudaFuncSetAttribute(flash_k,cudaFuncAttributeMaxDynamicSharedMemorySize,FSM);
    cudaFuncSetAttribute(gemm_k, cudaFuncAttributeMaxDynamicSharedMemorySize,GSM);

    cvt_all<<<8208,256>>>(x,Wq,Wk,Wv,Wd,mixing);                        // 0
    gemm_k<<<dim3(32,8,3),256,GSM>>>((const __nv_bfloat16*)xb,nullptr,bv,nullptr,nullptr,3); // 1
    prep8<<<12288,256>>>(x,Wcb);                                        // 2
    flash_k<<<dim3(32,HH,BB),256,FSM>>>();                              // 3 <- profiled
    gemm_k<<<dim3(32,8),256,GSM>>>((const __nv_bfloat16*)ctxb,(const __nv_bfloat16*)wdb,bd,x,resp,2); // 4
    ln_k<<<BSx,256>>>(gamma,beta,out);                                  // 5
}